// round 9
// baseline (speedup 1.0000x reference)
#include <cuda_runtime.h>

// Complex BatchNorm, B=16 fast path, OUTPUT = float32 REAL PART ONLY.
// R9: persistent-CTA grid-stride over the R8 float2 body (2 positions/thread,
// ~128 regs, 2 CTAs/SM). Grid = 304 CTAs (152 SMs x 2) -> single wave, no
// wave-transition or tail-quantization overhead. Default caching (R7 lesson).

#define EPS 1e-5f
#define PERSIST_CTAS 304   // 152 SMs x 2 resident CTAs

__global__ __launch_bounds__(256) void cbn_b16_v2_kernel(
    const float2* __restrict__ x_real,
    const float2* __restrict__ x_imag,
    const float2* __restrict__ g_rr,
    const float2* __restrict__ g_ri,
    const float2* __restrict__ beta,
    float2* __restrict__ out,
    int n2)   // n/2
{
    const int stride = gridDim.x * blockDim.x;
    for (int idx = blockIdx.x * blockDim.x + threadIdx.x; idx < n2; idx += stride) {

        float2 rv[16], iv[16];
        #pragma unroll
        for (int b = 0; b < 16; b++) {
            rv[b] = x_real[(size_t)b * n2 + idx];
            iv[b] = x_imag[(size_t)b * n2 + idx];
        }

        float2 grr2 = g_rr[idx];
        float2 gri2 = g_ri[idx];
        float2 bt2  = beta[idx];

        const float inv_b = 1.0f / 16.0f;

        #pragma unroll
        for (int lane = 0; lane < 2; lane++) {
            float sr = 0.f, si = 0.f;
            #pragma unroll
            for (int b = 0; b < 16; b++) {
                sr += ((const float*)&rv[b])[lane];
                si += ((const float*)&iv[b])[lane];
            }
            float mu_r = sr * inv_b, mu_i = si * inv_b;

            float vrr = 0.f, vii = 0.f, vri = 0.f;
            #pragma unroll
            for (int b = 0; b < 16; b++) {
                float rc = ((const float*)&rv[b])[lane] - mu_r;
                float ic = ((const float*)&iv[b])[lane] - mu_i;
                vrr = fmaf(rc, rc, vrr);
                vii = fmaf(ic, ic, vii);
                vri = fmaf(rc, ic, vri);
            }
            vrr = vrr * inv_b + EPS;
            vii = vii * inv_b + EPS;
            vri = vri * inv_b;

            float tau = vrr + vii;
            float s   = sqrtf(fmaf(vrr, vii, -vri * vri));
            float t   = sqrtf(tau + 2.0f * s);
            float inv_st = 1.0f / (s * t);
            float wrr = (vii + s) * inv_st;
            float wii = (vrr + s) * inv_st;
            float wri = -vri * inv_st;

            float grr = ((const float*)&grr2)[lane];
            float gri = ((const float*)&gri2)[lane];
            float bt  = ((const float*)&bt2)[lane];

            #pragma unroll
            for (int b = 0; b < 16; b++) {
                float rc = ((const float*)&rv[b])[lane] - mu_r;
                float ic = ((const float*)&iv[b])[lane] - mu_i;
                float nr = fmaf(wrr, rc, wri * ic);
                float ni = fmaf(wii, ic, wri * rc);
                ((float*)&rv[b])[lane] = fmaf(grr, nr, fmaf(gri, ni, bt));
            }
        }

        #pragma unroll
        for (int b = 0; b < 16; b++)
            out[(size_t)b * n2 + idx] = rv[b];
    }
}

// ---------- fallback paths (generic B / MODE 1 / ragged n) ----------

template <int MODE>
__global__ __launch_bounds__(256) void cbn_gen_kernel(
    const float* __restrict__ x_real,
    const float* __restrict__ x_imag,
    const float* __restrict__ g_rr,
    const float* __restrict__ g_ri,
    const float* __restrict__ g_ii,
    const float* __restrict__ beta,
    float* __restrict__ out_f,
    int n, int B, long long out_cap)
{
    int idx = blockIdx.x * blockDim.x + threadIdx.x;
    if (idx >= n) return;

    float sr = 0.f, si = 0.f, srr = 0.f, sii = 0.f, sri = 0.f;
    for (int b = 0; b < B; b++) {
        float rvv = x_real[(size_t)b * n + idx];
        float ivv = x_imag[(size_t)b * n + idx];
        sr += rvv; si += ivv;
        srr = fmaf(rvv, rvv, srr);
        sii = fmaf(ivv, ivv, sii);
        sri = fmaf(rvv, ivv, sri);
    }
    float inv_b = 1.0f / (float)B;
    float mu_r = sr * inv_b, mu_i = si * inv_b;
    float vrr = srr * inv_b - mu_r * mu_r + EPS;
    float vii = sii * inv_b - mu_i * mu_i + EPS;
    float vri = sri * inv_b - mu_r * mu_i;

    float tau = vrr + vii;
    float s   = sqrtf(fmaf(vrr, vii, -vri * vri));
    float t   = sqrtf(tau + 2.0f * s);
    float inv_st = 1.0f / (s * t);
    float wrr = (vii + s) * inv_st;
    float wii = (vrr + s) * inv_st;
    float wri = -vri * inv_st;

    float grr = g_rr[idx], gri = g_ri[idx], gii = g_ii[idx], bt = beta[idx];

    for (int b = 0; b < B; b++) {
        float rc = x_real[(size_t)b * n + idx] - mu_r;
        float ic = x_imag[(size_t)b * n + idx] - mu_i;
        float nr = fmaf(wrr, rc, wri * ic);
        float ni = fmaf(wii, ic, wri * rc);
        float re = fmaf(grr, nr, fmaf(gri, ni, bt));
        long long j = (long long)b * n + idx;
        if (MODE == 0) {
            if (j < out_cap) out_f[j] = re;
        } else {
            float ie = fmaf(gri, nr, fmaf(gii, ni, bt));
            long long f = 2 * j;
            if (f + 1 < out_cap) {
                float2 o; o.x = re; o.y = ie;
                *reinterpret_cast<float2*>(out_f + f) = o;
            } else if (f < out_cap) {
                out_f[f] = re;
            }
        }
    }
}

extern "C" void kernel_launch(void* const* d_in, const int* in_sizes, int n_in,
                              void* d_out, int out_size) {
    if (n_in < 6) return;

    long long small = in_sizes[0];
    for (int i = 1; i < n_in; i++)
        if ((long long)in_sizes[i] < small) small = in_sizes[i];

    const float* big_ptrs[8];   int n_big = 0;
    long long big_sz = small;
    const float* small_ptrs[8]; int n_small = 0;
    for (int i = 0; i < n_in && i < 8; i++) {
        if ((long long)in_sizes[i] == small) {
            small_ptrs[n_small++] = (const float*)d_in[i];
        } else {
            big_ptrs[n_big++] = (const float*)d_in[i];
            big_sz = in_sizes[i];
        }
    }
    if (n_big != 2 || n_small != 4) return;

    long long B_ll = big_sz / small;
    if (B_ll < 1 || B_ll > 65536 || small < 1) return;
    int n = (int)small;
    int B = (int)B_ll;

    const float* x_real = big_ptrs[0];
    const float* x_imag = big_ptrs[1];
    const float* g_rr = small_ptrs[0];
    const float* g_ri = small_ptrs[1];
    const float* g_ii = small_ptrs[2];
    const float* bt   = small_ptrs[3];
    float* out_f = (float*)d_out;
    long long out_cap = (long long)out_size;

    int mode = (out_cap == big_sz) ? 0 : 1;

    int threads = 256;

    if (B == 16 && mode == 0 && (n % 2) == 0 && out_cap >= big_sz) {
        int n2 = n / 2;
        int tiles = (n2 + threads - 1) / threads;
        int blocks = tiles < PERSIST_CTAS ? tiles : PERSIST_CTAS;
        cbn_b16_v2_kernel<<<blocks, threads>>>(
            (const float2*)x_real, (const float2*)x_imag,
            (const float2*)g_rr, (const float2*)g_ri, (const float2*)bt,
            (float2*)out_f, n2);
    } else {
        int blocks = (n + threads - 1) / threads;
        if (mode == 0)
            cbn_gen_kernel<0><<<blocks, threads>>>(x_real, x_imag,
                g_rr, g_ri, g_ii, bt, out_f, n, B, out_cap);
        else
            cbn_gen_kernel<1><<<blocks, threads>>>(x_real, x_imag,
                g_rr, g_ri, g_ii, bt, out_f, n, B, out_cap);
    }
}

// round 10
// speedup vs baseline: 1.0270x; 1.0270x over previous
#include <cuda_runtime.h>

// Complex BatchNorm, B=16, OUTPUT = float32 REAL PART ONLY.
// R10: half-warp batch split. Lanes 0-15 of each warp handle batches 0-7,
// lanes 16-31 handle batches 8-15, for the same 16 float2 positions.
// Raw moments combined across the half-warps with shfl.xor(16).
// Regs/thread ~halved vs R8 -> 3 CTAs/SM, 24 warps, same total traffic,
// all accesses remain 64-bit coalesced. Flat grid (persistent loop hurt, R9).

#define EPS 1e-5f

__global__ __launch_bounds__(256) void cbn_b16_split_kernel(
    const float2* __restrict__ x_real,
    const float2* __restrict__ x_imag,
    const float2* __restrict__ g_rr,
    const float2* __restrict__ g_ri,
    const float2* __restrict__ beta,
    float2* __restrict__ out,
    int n2)   // n/2, must be divisible by 16
{
    const int lane = threadIdx.x & 31;
    const int gwarp = (blockIdx.x * blockDim.x + threadIdx.x) >> 5;
    const int sub  = lane & 15;    // position slot within warp
    const int half = lane >> 4;    // batch half: 0 -> b 0..7, 1 -> b 8..15

    const int idx = gwarp * 16 + sub;
    if (idx >= n2) return;         // uniform across warp (n2 % 16 == 0)

    float2 rv[8], iv[8];
    const int b0 = half * 8;
    #pragma unroll
    for (int b = 0; b < 8; b++) {
        rv[b] = x_real[(size_t)(b0 + b) * n2 + idx];
        iv[b] = x_imag[(size_t)(b0 + b) * n2 + idx];
    }

    // raw partial moments per float2 component
    float sr0 = 0.f, si0 = 0.f, srr0 = 0.f, sii0 = 0.f, sri0 = 0.f;
    float sr1 = 0.f, si1 = 0.f, srr1 = 0.f, sii1 = 0.f, sri1 = 0.f;
    #pragma unroll
    for (int b = 0; b < 8; b++) {
        float r0 = rv[b].x, i0 = iv[b].x;
        float r1 = rv[b].y, i1 = iv[b].y;
        sr0 += r0; si0 += i0;
        srr0 = fmaf(r0, r0, srr0); sii0 = fmaf(i0, i0, sii0); sri0 = fmaf(r0, i0, sri0);
        sr1 += r1; si1 += i1;
        srr1 = fmaf(r1, r1, srr1); sii1 = fmaf(i1, i1, sii1); sri1 = fmaf(r1, i1, sri1);
    }

    // combine the two batch halves (partner lane = lane ^ 16, same idx)
    const unsigned m = 0xffffffffu;
    sr0  += __shfl_xor_sync(m, sr0, 16);  si0  += __shfl_xor_sync(m, si0, 16);
    srr0 += __shfl_xor_sync(m, srr0, 16); sii0 += __shfl_xor_sync(m, sii0, 16);
    sri0 += __shfl_xor_sync(m, sri0, 16);
    sr1  += __shfl_xor_sync(m, sr1, 16);  si1  += __shfl_xor_sync(m, si1, 16);
    srr1 += __shfl_xor_sync(m, srr1, 16); sii1 += __shfl_xor_sync(m, sii1, 16);
    sri1 += __shfl_xor_sync(m, sri1, 16);

    const float inv_b = 1.0f / 16.0f;

    float2 grr2 = g_rr[idx];
    float2 gri2 = g_ri[idx];
    float2 bt2  = beta[idx];

    // component 0
    float mu_r0 = sr0 * inv_b, mu_i0 = si0 * inv_b;
    float vrr0 = fmaf(srr0, inv_b, -mu_r0 * mu_r0) + EPS;
    float vii0 = fmaf(sii0, inv_b, -mu_i0 * mu_i0) + EPS;
    float vri0 = fmaf(sri0, inv_b, -mu_r0 * mu_i0);
    float s0 = sqrtf(fmaf(vrr0, vii0, -vri0 * vri0));
    float t0 = sqrtf(vrr0 + vii0 + 2.0f * s0);
    float inv_st0 = 1.0f / (s0 * t0);
    float wrr0 = (vii0 + s0) * inv_st0;
    float wii0 = (vrr0 + s0) * inv_st0;
    float wri0 = -vri0 * inv_st0;

    // component 1
    float mu_r1 = sr1 * inv_b, mu_i1 = si1 * inv_b;
    float vrr1 = fmaf(srr1, inv_b, -mu_r1 * mu_r1) + EPS;
    float vii1 = fmaf(sii1, inv_b, -mu_i1 * mu_i1) + EPS;
    float vri1 = fmaf(sri1, inv_b, -mu_r1 * mu_i1);
    float s1 = sqrtf(fmaf(vrr1, vii1, -vri1 * vri1));
    float t1 = sqrtf(vrr1 + vii1 + 2.0f * s1);
    float inv_st1 = 1.0f / (s1 * t1);
    float wrr1 = (vii1 + s1) * inv_st1;
    float wii1 = (vrr1 + s1) * inv_st1;
    float wri1 = -vri1 * inv_st1;

    #pragma unroll
    for (int b = 0; b < 8; b++) {
        float rc0 = rv[b].x - mu_r0, ic0 = iv[b].x - mu_i0;
        float nr0 = fmaf(wrr0, rc0, wri0 * ic0);
        float ni0 = fmaf(wii0, ic0, wri0 * rc0);
        float rc1 = rv[b].y - mu_r1, ic1 = iv[b].y - mu_i1;
        float nr1 = fmaf(wrr1, rc1, wri1 * ic1);
        float ni1 = fmaf(wii1, ic1, wri1 * rc1);
        float2 o;
        o.x = fmaf(grr2.x, nr0, fmaf(gri2.x, ni0, bt2.x));
        o.y = fmaf(grr2.y, nr1, fmaf(gri2.y, ni1, bt2.y));
        out[(size_t)(b0 + b) * n2 + idx] = o;
    }
}

// ---------- R8 float2 kernel (fallback for n2 % 16 != 0) ----------

__global__ __launch_bounds__(256) void cbn_b16_v2_kernel(
    const float2* __restrict__ x_real,
    const float2* __restrict__ x_imag,
    const float2* __restrict__ g_rr,
    const float2* __restrict__ g_ri,
    const float2* __restrict__ beta,
    float2* __restrict__ out,
    int n2)
{
    int idx = blockIdx.x * blockDim.x + threadIdx.x;
    if (idx >= n2) return;

    float2 rv[16], iv[16];
    #pragma unroll
    for (int b = 0; b < 16; b++) {
        rv[b] = x_real[(size_t)b * n2 + idx];
        iv[b] = x_imag[(size_t)b * n2 + idx];
    }

    float2 grr2 = g_rr[idx];
    float2 gri2 = g_ri[idx];
    float2 bt2  = beta[idx];
    const float inv_b = 1.0f / 16.0f;

    #pragma unroll
    for (int lane = 0; lane < 2; lane++) {
        float sr = 0.f, si = 0.f;
        #pragma unroll
        for (int b = 0; b < 16; b++) {
            sr += ((const float*)&rv[b])[lane];
            si += ((const float*)&iv[b])[lane];
        }
        float mu_r = sr * inv_b, mu_i = si * inv_b;

        float vrr = 0.f, vii = 0.f, vri = 0.f;
        #pragma unroll
        for (int b = 0; b < 16; b++) {
            float rc = ((const float*)&rv[b])[lane] - mu_r;
            float ic = ((const float*)&iv[b])[lane] - mu_i;
            vrr = fmaf(rc, rc, vrr);
            vii = fmaf(ic, ic, vii);
            vri = fmaf(rc, ic, vri);
        }
        vrr = vrr * inv_b + EPS;
        vii = vii * inv_b + EPS;
        vri = vri * inv_b;

        float s   = sqrtf(fmaf(vrr, vii, -vri * vri));
        float t   = sqrtf(vrr + vii + 2.0f * s);
        float inv_st = 1.0f / (s * t);
        float wrr = (vii + s) * inv_st;
        float wii = (vrr + s) * inv_st;
        float wri = -vri * inv_st;

        float grr = ((const float*)&grr2)[lane];
        float gri = ((const float*)&gri2)[lane];
        float bt  = ((const float*)&bt2)[lane];

        #pragma unroll
        for (int b = 0; b < 16; b++) {
            float rc = ((const float*)&rv[b])[lane] - mu_r;
            float ic = ((const float*)&iv[b])[lane] - mu_i;
            float nr = fmaf(wrr, rc, wri * ic);
            float ni = fmaf(wii, ic, wri * rc);
            ((float*)&rv[b])[lane] = fmaf(grr, nr, fmaf(gri, ni, bt));
        }
    }

    #pragma unroll
    for (int b = 0; b < 16; b++)
        out[(size_t)b * n2 + idx] = rv[b];
}

// ---------- generic fallback ----------

template <int MODE>
__global__ __launch_bounds__(256) void cbn_gen_kernel(
    const float* __restrict__ x_real,
    const float* __restrict__ x_imag,
    const float* __restrict__ g_rr,
    const float* __restrict__ g_ri,
    const float* __restrict__ g_ii,
    const float* __restrict__ beta,
    float* __restrict__ out_f,
    int n, int B, long long out_cap)
{
    int idx = blockIdx.x * blockDim.x + threadIdx.x;
    if (idx >= n) return;

    float sr = 0.f, si = 0.f, srr = 0.f, sii = 0.f, sri = 0.f;
    for (int b = 0; b < B; b++) {
        float rvv = x_real[(size_t)b * n + idx];
        float ivv = x_imag[(size_t)b * n + idx];
        sr += rvv; si += ivv;
        srr = fmaf(rvv, rvv, srr);
        sii = fmaf(ivv, ivv, sii);
        sri = fmaf(rvv, ivv, sri);
    }
    float inv_b = 1.0f / (float)B;
    float mu_r = sr * inv_b, mu_i = si * inv_b;
    float vrr = srr * inv_b - mu_r * mu_r + EPS;
    float vii = sii * inv_b - mu_i * mu_i + EPS;
    float vri = sri * inv_b - mu_r * mu_i;

    float s   = sqrtf(fmaf(vrr, vii, -vri * vri));
    float t   = sqrtf(vrr + vii + 2.0f * s);
    float inv_st = 1.0f / (s * t);
    float wrr = (vii + s) * inv_st;
    float wii = (vrr + s) * inv_st;
    float wri = -vri * inv_st;

    float grr = g_rr[idx], gri = g_ri[idx], gii = g_ii[idx], bt = beta[idx];

    for (int b = 0; b < B; b++) {
        float rc = x_real[(size_t)b * n + idx] - mu_r;
        float ic = x_imag[(size_t)b * n + idx] - mu_i;
        float nr = fmaf(wrr, rc, wri * ic);
        float ni = fmaf(wii, ic, wri * rc);
        float re = fmaf(grr, nr, fmaf(gri, ni, bt));
        long long j = (long long)b * n + idx;
        if (MODE == 0) {
            if (j < out_cap) out_f[j] = re;
        } else {
            float ie = fmaf(gri, nr, fmaf(gii, ni, bt));
            long long f = 2 * j;
            if (f + 1 < out_cap) {
                float2 o; o.x = re; o.y = ie;
                *reinterpret_cast<float2*>(out_f + f) = o;
            } else if (f < out_cap) {
                out_f[f] = re;
            }
        }
    }
}

extern "C" void kernel_launch(void* const* d_in, const int* in_sizes, int n_in,
                              void* d_out, int out_size) {
    if (n_in < 6) return;

    long long small = in_sizes[0];
    for (int i = 1; i < n_in; i++)
        if ((long long)in_sizes[i] < small) small = in_sizes[i];

    const float* big_ptrs[8];   int n_big = 0;
    long long big_sz = small;
    const float* small_ptrs[8]; int n_small = 0;
    for (int i = 0; i < n_in && i < 8; i++) {
        if ((long long)in_sizes[i] == small) {
            small_ptrs[n_small++] = (const float*)d_in[i];
        } else {
            big_ptrs[n_big++] = (const float*)d_in[i];
            big_sz = in_sizes[i];
        }
    }
    if (n_big != 2 || n_small != 4) return;

    long long B_ll = big_sz / small;
    if (B_ll < 1 || B_ll > 65536 || small < 1) return;
    int n = (int)small;
    int B = (int)B_ll;

    const float* x_real = big_ptrs[0];
    const float* x_imag = big_ptrs[1];
    const float* g_rr = small_ptrs[0];
    const float* g_ri = small_ptrs[1];
    const float* g_ii = small_ptrs[2];
    const float* bt   = small_ptrs[3];
    float* out_f = (float*)d_out;
    long long out_cap = (long long)out_size;

    int mode = (out_cap == big_sz) ? 0 : 1;
    int threads = 256;

    if (B == 16 && mode == 0 && (n % 2) == 0 && out_cap >= big_sz) {
        int n2 = n / 2;
        if ((n2 % 16) == 0) {
            // split kernel: each warp covers 16 float2 positions x 16 batches
            long long warps = n2 / 16;
            long long blocks = (warps + 7) / 8;   // 8 warps per 256-thread block
            cbn_b16_split_kernel<<<(int)blocks, threads>>>(
                (const float2*)x_real, (const float2*)x_imag,
                (const float2*)g_rr, (const float2*)g_ri, (const float2*)bt,
                (float2*)out_f, n2);
        } else {
            int blocks = (n2 + threads - 1) / threads;
            cbn_b16_v2_kernel<<<blocks, threads>>>(
                (const float2*)x_real, (const float2*)x_imag,
                (const float2*)g_rr, (const float2*)g_ri, (const float2*)bt,
                (float2*)out_f, n2);
        }
    } else {
        int blocks = (n + threads - 1) / threads;
        if (mode == 0)
            cbn_gen_kernel<0><<<blocks, threads>>>(x_real, x_imag,
                g_rr, g_ri, g_ii, bt, out_f, n, B, out_cap);
        else
            cbn_gen_kernel<1><<<blocks, threads>>>(x_real, x_imag,
                g_rr, g_ri, g_ii, bt, out_f, n, B, out_cap);
    }
}